// round 5
// baseline (speedup 1.0000x reference)
#include <cuda_runtime.h>
#include <cuda_bf16.h>
#include <cstdint>

#define N_ROWS   4194304
#define N_DIM    64
#define N_IMG    1024

// scratch accumulators (no allocation allowed; zero-initialized at load,
// invariant: re-zeroed by the last block of every launch)
__device__ float        g_sums[N_IMG * N_DIM];
__device__ int          g_counts[N_IMG];
__device__ unsigned int g_done;

#define BLOCKS   4096
#define THREADS  256
#define WARPS_PER_BLOCK (THREADS / 32)
#define ROWS_PER_WARP (N_ROWS / (BLOCKS * WARPS_PER_BLOCK))   // = 128

__global__ __launch_bounds__(THREADS, 4)
void main_kernel(const float* __restrict__ x,
                 const int* __restrict__ image_id,
                 float* __restrict__ out) {
    // ---- fused id copy: 4,194,304 ints / 4 per thread = exactly 1M threads
    {
        int tid = blockIdx.x * blockDim.x + threadIdx.x;   // 0 .. 1048575
        const int4* src = reinterpret_cast<const int4*>(image_id);
        float4* dst = reinterpret_cast<float4*>(out + N_IMG * N_DIM);
        int4 v = __ldcs(&src[tid]);
        __stcs(&dst[tid], make_float4((float)v.x, (float)v.y, (float)v.z, (float)v.w));
    }

    int gwarp = blockIdx.x * WARPS_PER_BLOCK + (threadIdx.x >> 5);
    int lane  = threadIdx.x & 31;
    int row0  = gwarp * ROWS_PER_WARP;

    int id_first = __ldg(&image_id[row0]);
    int id_last  = __ldg(&image_id[row0 + ROWS_PER_WARP - 1]);

    if (id_first == id_last) {
        // ---------------- FAST PATH (~97% of warps): single segment ----------
        int half = lane >> 4;        // 0: even rows, 1: odd rows
        int sub  = lane & 15;        // float4 slot within the row (4 dims)
        const float4* __restrict__ p =
            reinterpret_cast<const float4*>(x) +
            (size_t)(row0 + half) * (N_DIM / 4) + sub;

        // two independent accumulators -> half-depth FADD chains
        float4 a0 = make_float4(0.f, 0.f, 0.f, 0.f);
        float4 a1 = make_float4(0.f, 0.f, 0.f, 0.f);
        #pragma unroll 4
        for (int i = 0; i < ROWS_PER_WARP / 4; ++i) {
            float4 v0 = __ldcs(p + (size_t)(2 * i + 0) * (2 * N_DIM / 4));
            float4 v1 = __ldcs(p + (size_t)(2 * i + 1) * (2 * N_DIM / 4));
            a0.x += v0.x; a0.y += v0.y; a0.z += v0.z; a0.w += v0.w;
            a1.x += v1.x; a1.y += v1.y; a1.z += v1.z; a1.w += v1.w;
        }
        float4 acc = make_float4(a0.x + a1.x, a0.y + a1.y, a0.z + a1.z, a0.w + a1.w);
        // combine the two halves (lane l and l+16 hold the same 4 dims)
        acc.x += __shfl_down_sync(0xffffffff, acc.x, 16);
        acc.y += __shfl_down_sync(0xffffffff, acc.y, 16);
        acc.z += __shfl_down_sync(0xffffffff, acc.z, 16);
        acc.w += __shfl_down_sync(0xffffffff, acc.w, 16);
        if (half == 0) {
            float* s = &g_sums[id_first * N_DIM + sub * 4];
            atomicAdd(s + 0, acc.x);
            atomicAdd(s + 1, acc.y);
            atomicAdd(s + 2, acc.z);
            atomicAdd(s + 3, acc.w);
        }
        if (lane == 0) atomicAdd(&g_counts[id_first], ROWS_PER_WARP);
    } else {
        // ---------------- SLOW PATH (~3%): boundary inside the range ---------
        const float2* __restrict__ x2 = reinterpret_cast<const float2*>(x);
        float2 acc = make_float2(0.0f, 0.0f);
        int cur = id_first;
        int runlen = 0;

        for (int r = row0; r < row0 + ROWS_PER_WARP; ++r) {
            int id = __ldg(&image_id[r]);
            if (id != cur) {
                atomicAdd(&g_sums[cur * N_DIM + lane * 2 + 0], acc.x);
                atomicAdd(&g_sums[cur * N_DIM + lane * 2 + 1], acc.y);
                if (lane == 0) atomicAdd(&g_counts[cur], runlen);
                acc = make_float2(0.0f, 0.0f);
                cur = id;
                runlen = 0;
            }
            float2 v = __ldcs(&x2[(size_t)r * (N_DIM / 2) + lane]);
            acc.x += v.x;
            acc.y += v.y;
            ++runlen;
        }
        atomicAdd(&g_sums[cur * N_DIM + lane * 2 + 0], acc.x);
        atomicAdd(&g_sums[cur * N_DIM + lane * 2 + 1], acc.y);
        if (lane == 0) atomicAdd(&g_counts[cur], runlen);
    }

    // ---------------- last block: finalize + re-zero scratch -----------------
    __threadfence();
    __shared__ bool is_last;
    if (threadIdx.x == 0) {
        unsigned int v = atomicAdd(&g_done, 1u);
        is_last = (v == (unsigned)(BLOCKS - 1));
    }
    __syncthreads();
    if (is_last) {
        __threadfence();  // acquire side: all blocks' atomics now visible
        int tid = threadIdx.x;
        // averaged = sums / max(counts,1); re-zero sums in the same pass
        for (int i = tid; i < N_IMG * N_DIM; i += THREADS) {
            int c = __ldcg(&g_counts[i >> 6]);
            float s = __ldcg(&g_sums[i]);
            out[i] = s / (float)(c > 0 ? c : 1);
            g_sums[i] = 0.0f;
        }
        // counts -> tail of output
        for (int i = tid; i < N_IMG; i += THREADS) {
            out[N_IMG * N_DIM + N_ROWS + i] = (float)__ldcg(&g_counts[i]);
        }
        __syncthreads();   // counts fully consumed before zeroing
        for (int i = tid; i < N_IMG; i += THREADS) g_counts[i] = 0;
        if (tid == 0) g_done = 0u;
    }
}

// ---------------------------------------------------------------------------
extern "C" void kernel_launch(void* const* d_in, const int* in_sizes, int n_in,
                              void* d_out, int out_size) {
    const float* x = nullptr;
    const int* image_id = nullptr;
    for (int i = 0; i < n_in; ++i) {
        if (in_sizes[i] == N_ROWS * N_DIM) x = (const float*)d_in[i];
        else if (in_sizes[i] == N_ROWS)    image_id = (const int*)d_in[i];
    }
    float* out = (float*)d_out;

    main_kernel<<<BLOCKS, THREADS>>>(x, image_id, out);
}

// round 6
// speedup vs baseline: 1.4935x; 1.4935x over previous
#include <cuda_runtime.h>
#include <cuda_bf16.h>
#include <cstdint>

#define N_ROWS   4194304
#define N_DIM    64
#define N_IMG    1024

// scratch accumulators (no allocation allowed; zero-initialized at load,
// invariant: re-zeroed by finalize_kernel at the end of every launch)
__device__ float g_sums[N_IMG * N_DIM];
__device__ int   g_counts[N_IMG];

// single-wave persistent grid: 512 blocks < 148 SMs * 4 blocks residency
#define BLOCKS   512
#define THREADS  256
#define WARPS_PER_BLOCK (THREADS / 32)
#define N_WARPS  (BLOCKS * WARPS_PER_BLOCK)              // 4096
#define ROWS_PER_WARP (N_ROWS / N_WARPS)                 // 1024
#define CHUNK    128
#define CHUNKS   (ROWS_PER_WARP / CHUNK)                 // 8

__global__ __launch_bounds__(THREADS, 4)
void main_kernel(const float* __restrict__ x,
                 const int* __restrict__ image_id,
                 float* __restrict__ out) {
    // ---- fused id copy: 1M int4's over 131072 threads -> 8 int4 each
    {
        int tid = blockIdx.x * blockDim.x + threadIdx.x;   // 0 .. 131071
        const int4* src = reinterpret_cast<const int4*>(image_id);
        float4* dst = reinterpret_cast<float4*>(out + N_IMG * N_DIM);
        #pragma unroll
        for (int k = 0; k < (N_ROWS / 4) / (BLOCKS * THREADS); ++k) {
            int i = tid + k * (BLOCKS * THREADS);
            int4 v = __ldcs(&src[i]);
            dst[i] = make_float4((float)v.x, (float)v.y, (float)v.z, (float)v.w);
        }
    }

    int gwarp = blockIdx.x * WARPS_PER_BLOCK + (threadIdx.x >> 5);
    int lane  = threadIdx.x & 31;
    int row0  = gwarp * ROWS_PER_WARP;

    // persistent per-lane accumulator layout:
    //   half = lane>>4 (even/odd row of each pair), sub = lane&15 (4 dims)
    int half = lane >> 4;
    int sub  = lane & 15;
    const float4* __restrict__ x4 = reinterpret_cast<const float4*>(x);
    const float2* __restrict__ x2 = reinterpret_cast<const float2*>(x);

    float4 acc = make_float4(0.f, 0.f, 0.f, 0.f);
    int cur = -1;
    int runlen = 0;

    // warp-uniform flush of the float4 accumulator
    #define FLUSH()                                                          \
        do {                                                                 \
            if (runlen > 0) {                                                \
                float4 t = acc;                                              \
                t.x += __shfl_down_sync(0xffffffff, t.x, 16);                \
                t.y += __shfl_down_sync(0xffffffff, t.y, 16);                \
                t.z += __shfl_down_sync(0xffffffff, t.z, 16);                \
                t.w += __shfl_down_sync(0xffffffff, t.w, 16);                \
                if (half == 0) {                                             \
                    float* s = &g_sums[cur * N_DIM + sub * 4];               \
                    atomicAdd(s + 0, t.x);                                   \
                    atomicAdd(s + 1, t.y);                                   \
                    atomicAdd(s + 2, t.z);                                   \
                    atomicAdd(s + 3, t.w);                                   \
                }                                                            \
                if (lane == 0) atomicAdd(&g_counts[cur], runlen);            \
                acc = make_float4(0.f, 0.f, 0.f, 0.f);                       \
                runlen = 0;                                                  \
            }                                                                \
        } while (0)

    for (int c = 0; c < CHUNKS; ++c) {
        int rc  = row0 + c * CHUNK;
        int ida = __ldg(&image_id[rc]);
        int idb = __ldg(&image_id[rc + CHUNK - 1]);

        if (ida == idb) {
            // ---- fast chunk (~97%): uniform segment over 128 rows
            if (ida != cur) { FLUSH(); cur = ida; }
            const float4* __restrict__ p =
                x4 + (size_t)(rc + half) * (N_DIM / 4) + sub;
            float4 a0 = make_float4(0.f, 0.f, 0.f, 0.f);
            float4 a1 = make_float4(0.f, 0.f, 0.f, 0.f);
            #pragma unroll 4
            for (int i = 0; i < CHUNK / 4; ++i) {
                float4 v0 = __ldcs(p + (size_t)(2 * i + 0) * (2 * N_DIM / 4));
                float4 v1 = __ldcs(p + (size_t)(2 * i + 1) * (2 * N_DIM / 4));
                a0.x += v0.x; a0.y += v0.y; a0.z += v0.z; a0.w += v0.w;
                a1.x += v1.x; a1.y += v1.y; a1.z += v1.z; a1.w += v1.w;
            }
            acc.x += a0.x + a1.x;
            acc.y += a0.y + a1.y;
            acc.z += a0.z + a1.z;
            acc.w += a0.w + a1.w;
            runlen += CHUNK;
        } else {
            // ---- slow chunk (~3%): boundary inside; per-row float2 layout
            FLUSH();
            float2 sacc = make_float2(0.f, 0.f);
            int scur = ida;
            int srun = 0;
            for (int r = rc; r < rc + CHUNK; ++r) {
                int id = __ldg(&image_id[r]);
                if (id != scur) {
                    atomicAdd(&g_sums[scur * N_DIM + lane * 2 + 0], sacc.x);
                    atomicAdd(&g_sums[scur * N_DIM + lane * 2 + 1], sacc.y);
                    if (lane == 0) atomicAdd(&g_counts[scur], srun);
                    sacc = make_float2(0.f, 0.f);
                    scur = id;
                    srun = 0;
                }
                float2 v = __ldcs(&x2[(size_t)r * (N_DIM / 2) + lane]);
                sacc.x += v.x;
                sacc.y += v.y;
                ++srun;
            }
            atomicAdd(&g_sums[scur * N_DIM + lane * 2 + 0], sacc.x);
            atomicAdd(&g_sums[scur * N_DIM + lane * 2 + 1], sacc.y);
            if (lane == 0) atomicAdd(&g_counts[scur], srun);
            cur = -1;   // force re-sync of fast-path segment id
        }
    }
    FLUSH();
    #undef FLUSH
}

// ---------------------------------------------------------------------------
// finalize: averaged -> out[0:65536], counts -> tail; re-zero scratch for the
// next graph replay (restores the load-time invariant).
// ---------------------------------------------------------------------------
__global__ void finalize_kernel(float* __restrict__ out) {
    int tid = blockIdx.x * blockDim.x + threadIdx.x;
    if (tid < N_IMG * N_DIM) {
        int img = tid >> 6;  // /64
        int c = g_counts[img];
        float denom = (float)(c > 0 ? c : 1);
        out[tid] = g_sums[tid] / denom;
        g_sums[tid] = 0.0f;
    }
    if (tid < N_IMG) {
        out[N_IMG * N_DIM + N_ROWS + tid] = (float)g_counts[tid];
    }
    // zero counts from a disjoint thread range (no race with readers above:
    // reader of g_counts[img] for tid in [0,65536) uses img = tid>>6, and the
    // zeroing threads are tid in [65536, 65536+1024) -> different threads may
    // race across blocks, so do it in a second pass guarded by a grid-wide
    // ordering: instead, zero counts ONLY from the same thread that wrote the
    // tail value (it has already consumed the count).
    if (tid < N_IMG) {
        // tail write above already read g_counts[tid]; but other threads
        // (tid*64 .. tid*64+63) also read it for the average. Those reads
        // happen in this same kernel with no ordering. To stay safe, counts
        // zeroing is deferred to the helper below.
    }
}

// tiny helper: zero counts after finalize has consumed them
__global__ void zero_counts_kernel() {
    int tid = blockIdx.x * blockDim.x + threadIdx.x;
    if (tid < N_IMG) g_counts[tid] = 0;
}

// ---------------------------------------------------------------------------
extern "C" void kernel_launch(void* const* d_in, const int* in_sizes, int n_in,
                              void* d_out, int out_size) {
    const float* x = nullptr;
    const int* image_id = nullptr;
    for (int i = 0; i < n_in; ++i) {
        if (in_sizes[i] == N_ROWS * N_DIM) x = (const float*)d_in[i];
        else if (in_sizes[i] == N_ROWS)    image_id = (const int*)d_in[i];
    }
    float* out = (float*)d_out;

    main_kernel<<<BLOCKS, THREADS>>>(x, image_id, out);
    finalize_kernel<<<(N_IMG * N_DIM + 255) / 256, 256>>>(out);
    zero_counts_kernel<<<4, 256>>>();
}